// round 15
// baseline (speedup 1.0000x reference)
#include <cuda_runtime.h>
#include <cuda_fp16.h>
#include <cstdint>

#define NOISE_SCALE (8.0f/255.0f)
#define K_SEL 64

__device__ float g_bias[256];                         // NOISE_SCALE * sum|w|
__device__ __half g_Aexp[2 * 9 * 256 * 128];          // [comp][kk][cout][cin]

// ---------------- smem layout (bytes) ----------------
#define SM_AH  0                       // whi  [256 m][128 k] halves, 256B rows = 64KB
#define SM_AL  65536                   // wlo' [256 m][128 k] halves           = 64KB
#define SM_XH  131072                  // xh: 193 rows x 256B (row 0 zeros)
#define SM_XL  180480                  // xl'
#define XL_DELTA 49408
#define FUSED_SMEM 229888              // 224.5KB
#define OS_OFF 0                       // epilogue overlay: os[64][257] f32 (65792B)
#define TH_OFF 66048                   // th[64] u32

__device__ __forceinline__ uint32_t smem_u32(const void* p) {
    uint32_t a;
    asm("{ .reg .u64 t; cvta.to.shared.u64 t, %1; cvt.u32.u64 %0, t; }" : "=r"(a) : "l"(p));
    return a;
}
__device__ __forceinline__ unsigned ordmap(float f) {
    int s = __float_as_int(f);
    return (unsigned)(s ^ ((s >> 31) | 0x80000000));
}

#define CP_ASYNC16(dst, src) \
    asm volatile("cp.async.ca.shared.global [%0], [%1], 16;" :: "r"(dst), "l"(src))
#define CP_COMMIT() asm volatile("cp.async.commit_group;" ::: "memory")
#define CP_WAIT0()  asm volatile("cp.async.wait_group 0;" ::: "memory")

#define LDMX4(r0,r1,r2,r3,ad) \
    asm volatile("ldmatrix.sync.aligned.m8n8.x4.shared.b16 {%0,%1,%2,%3}, [%4];" \
        : "=r"(r0),"=r"(r1),"=r"(r2),"=r"(r3) : "r"(ad))
#define MMA16816(c, a, b0v, b1v) \
    asm volatile("mma.sync.aligned.m16n8k16.row.col.f32.f16.f16.f32 " \
        "{%0,%1,%2,%3}, {%4,%5,%6,%7}, {%8,%9}, {%0,%1,%2,%3};" \
        : "+f"((c)[0]), "+f"((c)[1]), "+f"((c)[2]), "+f"((c)[3]) \
        : "r"((a)[0]), "r"((a)[1]), "r"((a)[2]), "r"((a)[3]), "r"(b0v), "r"(b1v))

// ---------------- prep: g_bias[c] = NOISE_SCALE * sum |w[c,:,:,:]| ----------
__global__ void bias_kernel(const float* __restrict__ w) {
    int c = blockIdx.x, t = threadIdx.x;
    float s = 0.f;
    #pragma unroll
    for (int k = 0; k < 9; k++) s += fabsf(w[c * 1152 + k * 128 + t]);
    __shared__ float red[128];
    red[t] = s;
    __syncthreads();
    #pragma unroll
    for (int off = 64; off > 0; off >>= 1) {
        if (t < off) red[t] += red[t + off];
        __syncthreads();
    }
    if (t == 0) g_bias[c] = red[0] * NOISE_SCALE;
}

// ---------------- prep: fp16 hi/lo split weights ----------------
__global__ void wexpand_kernel(const float* __restrict__ w) {
    int co = blockIdx.x;
    for (int idx = threadIdx.x; idx < 1152; idx += blockDim.x) {
        int kk = idx >> 7, cin = idx & 127;
        float v = w[co * 1152 + cin * 9 + kk];
        __half hi = __float2half_rn(v);
        __half lo = __float2half_rn((v - __half2float(hi)) * 2048.0f);
        g_Aexp[((size_t)kk * 256 + co) * 128 + cin] = hi;
        g_Aexp[(size_t)9 * 256 * 128 + ((size_t)kk * 256 + co) * 128 + cin] = lo;
    }
}

// ---------------- fused: conv (M=256 x N=64) + noise + topk + relu ----------
__global__ __launch_bounds__(512)
void fused_kernel(const float* __restrict__ x,
                  const float* __restrict__ noise,
                  const float* __restrict__ relu_bias,
                  float* __restrict__ out) {
    extern __shared__ char smem[];
    const uint32_t sb = smem_u32(smem);
    const int tid = threadIdx.x;
    const int wid = tid >> 5, lane = tid & 31;
    const int wm = wid & 7, wn = wid >> 3;       // 8 M-warps x 2 N-warps (warp tile 32x32)
    const int h0 = blockIdx.x;                   // 0-63
    const int b = blockIdx.y;                    // 0-31

    float acc1[2][4][4], acc2[2][4][4];
    #pragma unroll
    for (int i = 0; i < 2; i++)
        #pragma unroll
        for (int j = 0; j < 4; j++)
            #pragma unroll
            for (int k = 0; k < 4; k++) { acc1[i][j][k] = 0.f; acc2[i][j][k] = 0.f; }

    const int mlA = lane & 15, kbA = lane >> 4;               // A ldmatrix roles
    const int nloc = (lane & 7) + ((lane >> 4) & 1) * 8;      // B row-in-16 group
    const uint32_t kofb = (uint32_t)(((lane >> 3) & 1) * 16); // B 16B k-offset

    // ---- zero row 0 of both x buffers ----
    if (tid < 64) {
        *(uint32_t*)(smem + SM_XH + tid * 4) = 0u;
        *(uint32_t*)(smem + SM_XL + tid * 4) = 0u;
    }

    // ---- A staging roles; prefetch whi(kk=0) ----
    const int am = tid >> 1, aq = tid & 1;       // row am (0-255), k-half aq
    {
        const __half* Ac = g_Aexp + ((size_t)am) * 128 + aq * 64;
        #pragma unroll
        for (int j = 0; j < 8; j++) {
            const uint32_t dst = sb + SM_AH + am * 256 +
                                 (uint32_t)(((aq * 8 + j) ^ (am & 7)) * 16);
            CP_ASYNC16(dst, Ac + j * 8);
        }
        CP_COMMIT();
    }

    // ---- stage x once: 3 image rows (h0-1..h0+1) x 128 cin, transposed ----
    {
        #pragma unroll 1
        for (int i = 0; i < 12; i++) {
            const int g = tid + 512 * i;          // 0..6143
            const int row = g >> 4;               // (slot, cin): 0..383
            const int f4i = g & 15;
            const int s = row >> 7, cin = row & 127;
            const int hh = h0 - 1 + s;
            if (hh < 0 || hh > 63) continue;
            float4 v = *(const float4*)(x + (((size_t)b * 128 + cin) * 64 + hh) * 64 + f4i * 4);
            float fv[4] = {v.x, v.y, v.z, v.w};
            const uint32_t colh = (uint32_t)(cin >> 3);
            const uint32_t cofs = (uint32_t)((cin & 7) * 2);
            #pragma unroll
            for (int e = 0; e < 4; e++) {
                const int w = f4i * 4 + e;
                const int smrow = 1 + s * 64 + w;
                const uint32_t ad = (uint32_t)(smrow * 256) +
                                    ((colh ^ (uint32_t)(smrow & 7)) * 16) + cofs;
                __half hi = __float2half_rn(fv[e]);
                __half lo = __float2half_rn((fv[e] - __half2float(hi)) * 2048.0f);
                *(__half*)(smem + SM_XH + ad) = hi;
                *(__half*)(smem + SM_XL + ad) = lo;
            }
        }
    }

    // ---- main loop over 9 taps ----
    #pragma unroll 1
    for (int kk = 0; kk < 9; kk++) {
        const int ky = kk / 3, kx = kk % 3;

        CP_WAIT0();
        __syncthreads();   // whi(kk) ready; x ready (kk=0); prior wlo reads done

        // prefetch wlo'(kk)
        {
            const __half* Ac = g_Aexp + (size_t)9 * 256 * 128
                             + ((size_t)kk * 256 + am) * 128 + aq * 64;
            #pragma unroll
            for (int j = 0; j < 8; j++) {
                const uint32_t dst = sb + SM_AL + am * 256 +
                                     (uint32_t)(((aq * 8 + j) ^ (am & 7)) * 16);
                CP_ASYNC16(dst, Ac + j * 8);
            }
            CP_COMMIT();
        }

        // per-lane B row addresses for this tap
        uint32_t baseH[2], par16[2];
        {
            const int hh = h0 + ky - 1;
            const bool hv = (hh >= 0) && (hh < 64);
            #pragma unroll
            for (int p = 0; p < 2; p++) {
                const int w = wn * 32 + p * 16 + nloc + kx - 1;
                const int rowidx = (hv && w >= 0 && w < 64) ? (1 + ky * 64 + w) : 0;
                baseH[p] = sb + SM_XH + (uint32_t)(rowidx * 256);
                par16[p] = (uint32_t)((rowidx & 7) * 16);
            }
        }

        // ---- phase A: whi x (xh -> acc1, xl' -> acc2) ----
        #pragma unroll
        for (int ks = 0; ks < 8; ks++) {
            uint32_t ahi[2][4];
            #pragma unroll
            for (int mt = 0; mt < 2; mt++) {
                const int m = wm * 32 + mt * 16 + mlA;
                const uint32_t c = (uint32_t)(((ks * 2 + kbA) ^ (m & 7)) * 16);
                LDMX4(ahi[mt][0], ahi[mt][1], ahi[mt][2], ahi[mt][3],
                      sb + SM_AH + (uint32_t)(m * 256) + c);
            }
            #pragma unroll
            for (int p = 0; p < 2; p++) {
                const uint32_t adH = baseH[p] + (((uint32_t)(ks * 32) + kofb) ^ par16[p]);
                uint32_t bh[4], bl[4];
                LDMX4(bh[0], bh[1], bh[2], bh[3], adH);
                LDMX4(bl[0], bl[1], bl[2], bl[3], adH + XL_DELTA);
                #pragma unroll
                for (int mt = 0; mt < 2; mt++) {
                    MMA16816(acc1[mt][p * 2],     ahi[mt], bh[0], bh[1]);
                    MMA16816(acc1[mt][p * 2 + 1], ahi[mt], bh[2], bh[3]);
                    MMA16816(acc2[mt][p * 2],     ahi[mt], bl[0], bl[1]);
                    MMA16816(acc2[mt][p * 2 + 1], ahi[mt], bl[2], bl[3]);
                }
            }
        }

        CP_WAIT0();
        __syncthreads();   // wlo'(kk) ready; phase-A reads of SM_AH done

        // prefetch whi(kk+1)
        if (kk < 8) {
            const __half* Ac = g_Aexp + ((size_t)(kk + 1) * 256 + am) * 128 + aq * 64;
            #pragma unroll
            for (int j = 0; j < 8; j++) {
                const uint32_t dst = sb + SM_AH + am * 256 +
                                     (uint32_t)(((aq * 8 + j) ^ (am & 7)) * 16);
                CP_ASYNC16(dst, Ac + j * 8);
            }
            CP_COMMIT();
        }

        // ---- phase B: wlo' x xh -> acc2 ----
        #pragma unroll
        for (int ks = 0; ks < 8; ks++) {
            uint32_t alo[2][4];
            #pragma unroll
            for (int mt = 0; mt < 2; mt++) {
                const int m = wm * 32 + mt * 16 + mlA;
                const uint32_t c = (uint32_t)(((ks * 2 + kbA) ^ (m & 7)) * 16);
                LDMX4(alo[mt][0], alo[mt][1], alo[mt][2], alo[mt][3],
                      sb + SM_AL + (uint32_t)(m * 256) + c);
            }
            #pragma unroll
            for (int p = 0; p < 2; p++) {
                const uint32_t adH = baseH[p] + (((uint32_t)(ks * 32) + kofb) ^ par16[p]);
                uint32_t bh[4];
                LDMX4(bh[0], bh[1], bh[2], bh[3], adH);
                #pragma unroll
                for (int mt = 0; mt < 2; mt++) {
                    MMA16816(acc2[mt][p * 2],     alo[mt], bh[0], bh[1]);
                    MMA16816(acc2[mt][p * 2 + 1], alo[mt], bh[2], bh[3]);
                }
            }
        }
    }

    // ---- epilogue: overlay os[64][257] on dead A smem ----
    __syncthreads();   // all MMA + smem reads done
    float* os = (float*)(smem + OS_OFF);
    unsigned* th = (unsigned*)(smem + TH_OFF);
    const float RS = 4.8828125e-4f;   // 2^-11

    #pragma unroll
    for (int mt = 0; mt < 2; mt++) {
        const int co = wm * 32 + mt * 16 + (lane >> 2);
        #pragma unroll
        for (int nt = 0; nt < 4; nt++) {
            const int n = wn * 32 + nt * 8 + (lane & 3) * 2;
            os[n * 257 + co]           = acc1[mt][nt][0] + acc2[mt][nt][0] * RS;
            os[(n + 1) * 257 + co]     = acc1[mt][nt][1] + acc2[mt][nt][1] * RS;
            os[n * 257 + co + 8]       = acc1[mt][nt][2] + acc2[mt][nt][2] * RS;
            os[(n + 1) * 257 + co + 8] = acc1[mt][nt][3] + acc2[mt][nt][3] * RS;
        }
    }
    __syncthreads();

    // noise add (g_bias pre-scaled by NOISE_SCALE)
    {
        const float* nb = noise + (size_t)b * 256 * 4096 + h0 * 64;
        for (int idx = tid; idx < 256 * 64; idx += 512) {
            int c = idx >> 6, w = idx & 63;
            float u = nb[c * 4096 + w];
            os[w * 257 + c] = fmaf(g_bias[c], 2.0f * u - 1.0f, os[w * 257 + c]);
        }
    }
    __syncthreads();

    // per-pixel 64th-largest via 32-step bitwise radix select (1 warp/pixel)
    #pragma unroll 1
    for (int pp = 0; pp < 4; pp++) {
        const int p = wid * 4 + pp;
        unsigned uv[8];
        #pragma unroll
        for (int j = 0; j < 8; j++)
            uv[j] = ordmap(os[p * 257 + lane * 8 + j]);
        unsigned X = 0;
        #pragma unroll 1
        for (int bit = 31; bit >= 0; bit--) {
            unsigned cand = X | (1u << bit);
            int cnt = 0;
            #pragma unroll
            for (int j = 0; j < 8; j++) cnt += (uv[j] >= cand) ? 1 : 0;
            int tot = __reduce_add_sync(0xffffffffu, cnt);
            if (tot >= K_SEL) X = cand;
        }
        if (lane == 0) th[p] = X;
    }
    __syncthreads();

    // threshold + relu_bias + relu, coalesced store
    {
        float* ob = out + (size_t)b * 256 * 4096 + h0 * 64;
        for (int idx = tid; idx < 256 * 64; idx += 512) {
            int c = idx >> 6, w = idx & 63;
            float v = os[w * 257 + c];
            float keep = (ordmap(v) >= th[w]) ? v : 0.f;
            ob[c * 4096 + w] = fmaxf(keep + __ldg(relu_bias + c), 0.f);
        }
    }
}

// ---------------- launch ----------------
extern "C" void kernel_launch(void* const* d_in, const int* in_sizes, int n_in,
                              void* d_out, int out_size) {
    const float* x         = (const float*)d_in[0];
    const float* weight    = (const float*)d_in[1];
    const float* relu_bias = (const float*)d_in[2];
    const float* noise     = (const float*)d_in[3];
    float* out = (float*)d_out;

    wexpand_kernel<<<256, 256>>>(weight);
    bias_kernel<<<256, 128>>>(weight);

    cudaFuncSetAttribute(fused_kernel,
                         cudaFuncAttributeMaxDynamicSharedMemorySize, FUSED_SMEM);
    fused_kernel<<<dim3(64, 32), 512, FUSED_SMEM>>>(x, noise, relu_bias, out);
}